// round 13
// baseline (speedup 1.0000x reference)
#include <cuda_runtime.h>

// RNN_64501818851829 — GB300 sm_103a. Round 13.
// Fused recurrence (R9): a(t)=lrelu(W1u·u+M·a(t-1)+c), o(t)=lrelu(OW1u·u+N·a+d),
// out=ow2·o+ob2, M=W1h·W2, N=OW1h·W2 (prologue-computed).
// NEW: fused weights live in REGISTERS, 50 floats/thread.
//   1024 blocks x 64 threads, 4 rows (2 f32x2 pairs)/block.
//   warp0 = h2h neurons 0..39 -> a(t); warp1 = h2o -> out(t) inline.
//   Lane (jg=l>>2: 5 neurons, kq=l&3: 10-k quarter). k-quarters combined
//   with warp shuffles (xor 1,2); out-dot reduced with shuffles (xor 4,8,16).
//   Weight LDS in main loop: ZERO. One __syncthreads per step.

typedef unsigned long long u64;

static constexpr int Tn = 1024;
static constexpr int NTHR = 64;
static constexpr int NBLK = 1024;          // 4 rows per block

__device__ __forceinline__ u64 fma2(u64 a, u64 b, u64 c) {
    u64 d; asm("fma.rn.f32x2 %0, %1, %2, %3;" : "=l"(d) : "l"(a), "l"(b), "l"(c));
    return d;
}
__device__ __forceinline__ u64 add2(u64 a, u64 b) {
    u64 d; asm("add.rn.f32x2 %0, %1, %2;" : "=l"(d) : "l"(a), "l"(b));
    return d;
}
__device__ __forceinline__ u64 mul2(u64 a, u64 b) {
    u64 d; asm("mul.rn.f32x2 %0, %1, %2;" : "=l"(d) : "l"(a), "l"(b));
    return d;
}
__device__ __forceinline__ u64 pack2(float lo, float hi) {
    u64 d; asm("mov.b64 %0, {%1, %2};" : "=l"(d) : "f"(lo), "f"(hi));
    return d;
}
__device__ __forceinline__ void unpack2(u64 v, float& lo, float& hi) {
    asm("mov.b64 {%0, %1}, %2;" : "=f"(lo), "=f"(hi) : "l"(v));
}
__device__ __forceinline__ u64 dupf(float x) {
    u64 d; asm("mov.b64 %0, {%1, %1};" : "=l"(d) : "f"(x));
    return d;
}
// exact leaky-relu(0.01): max(x, 0.01*x)
__device__ __forceinline__ u64 lrelu2(u64 x, u64 c001) {
    u64 m = mul2(x, c001);
    float2 xf = *(float2*)&x, mf = *(float2*)&m, r;
    r.x = fmaxf(xf.x, mf.x);
    r.y = fmaxf(xf.y, mf.y);
    return *(u64*)&r;
}
__device__ __forceinline__ u64 shfl_xor64(u64 v, int m) {
    return __shfl_xor_sync(0xffffffffu, v, m);
}

__global__ void __launch_bounds__(NTHR, 7) rnn_kernel(
    const float* __restrict__ inputs,
    const float* __restrict__ w1,  const float* __restrict__ b1,
    const float* __restrict__ w2,  const float* __restrict__ b2,
    const float* __restrict__ ow1, const float* __restrict__ ob1,
    const float* __restrict__ ow2, const float* __restrict__ ob2,
    float* __restrict__ outp)
{
    __shared__ float sW2f[40 * 40];                 // prologue only
    __shared__ __align__(16) u64 sZ[2][2][42];      // [buf][pair][0..39 z, 40=u]

    const int tid = threadIdx.x;
    const int wid = tid >> 5;      // 0 = h2h (produces a), 1 = h2o (produces out)
    const int l   = tid & 31;
    const int jg  = l >> 2;        // 0..7 -> 5 neurons
    const int kq  = l & 3;         // k-quarter -> 10 k's
    const int j0  = 5 * jg;
    const int k0  = 10 * kq;
    const int baseRow = blockIdx.x * 4;
    const u64 c001 = dupf(0.01f);

    // ---- stage w2 ----
    for (int i = tid; i < 1600; i += NTHR) sW2f[i] = w2[i];
    __syncthreads();

    // this thread's 5 L1 rows (hidden part, cols 1..40) of its half
    const float* wrow = (wid == 0) ? (w1 + j0 * 41 + 1)
                                   : (ow1 + j0 * 41 + 1);

    // ---- prologue: per-thread fused weights wr[5][10] = (W1h @ W2) slice ----
    float wr[5][10];
    float cd[5];
#pragma unroll
    for (int i = 0; i < 5; i++) {
        cd[i] = 0.0f;
#pragma unroll
        for (int q = 0; q < 10; q++) wr[i][q] = 0.0f;
    }
    for (int m = 0; m < 40; m++) {
        float av[5];
#pragma unroll
        for (int i = 0; i < 5; i++) av[i] = wrow[i * 41 + m];
        float bm = b2[m];
        float wv[10];
#pragma unroll
        for (int q = 0; q < 10; q++) wv[q] = sW2f[m * 40 + k0 + q];
#pragma unroll
        for (int i = 0; i < 5; i++) {
            cd[i] += av[i] * bm;
#pragma unroll
            for (int q = 0; q < 10; q++) wr[i][q] += av[i] * wv[q];
        }
    }

    // ---- zero-padded per-lane constants (keeps the GEMV warp-uniform) ----
    // bAz: fused bias on kq==0 lanes, else 0 (acc init).
    // wUz: u-column weight on kq==3 lanes, else 0 (u-term).
    // rW : out-dot weights (warp1).
    u64 bAz[5], wUz[5], rW[5];
#pragma unroll
    for (int i = 0; i < 5; i++) {
        float pb = (wid == 0) ? b1[j0 + i] : ob1[j0 + i];
        bAz[i] = (kq == 0) ? dupf(cd[i] + pb) : 0ull;
        float uw = (wid == 0) ? w1[(j0 + i) * 41] : ow1[(j0 + i) * 41];
        wUz[i] = (kq == 3) ? dupf(uw) : 0ull;
        rW[i]  = (wid == 1) ? dupf(ow2[j0 + i]) : 0ull;
    }
    const u64 bo = dupf(ob2[0]);

    // ---- step t = 0 (h = 0: plain biases, u-column only) ----
    {
        u64 u0[2];
#pragma unroll
        for (int p = 0; p < 2; p++) {
            int ra = baseRow + 2 * p;
            u0[p] = pack2(inputs[(size_t)ra * Tn], inputs[(size_t)(ra + 1) * Tn]);
        }
        if (wid == 0) {
#pragma unroll
            for (int i = 0; i < 5; i++) {
                if (i == kq || (kq == 0 && i == 4)) {
                    int n = j0 + i;
                    u64 w = dupf(w1[n * 41]);
                    u64 b = dupf(b1[n]);
                    sZ[0][0][n] = lrelu2(fma2(u0[0], w, b), c001);
                    sZ[0][1][n] = lrelu2(fma2(u0[1], w, b), c001);
                }
            }
        } else {
            u64 d0 = 0ull, d1 = 0ull;
#pragma unroll
            for (int i = 0; i < 5; i++) {
                int n = j0 + i;
                u64 w = dupf(ow1[n * 41]);
                u64 b = dupf(ob1[n]);
                u64 z0 = lrelu2(fma2(u0[0], w, b), c001);
                u64 z1 = lrelu2(fma2(u0[1], w, b), c001);
                d0 = fma2(z0, rW[i], d0);
                d1 = fma2(z1, rW[i], d1);
            }
#pragma unroll
            for (int off = 4; off < 32; off <<= 1) {
                d0 = add2(d0, shfl_xor64(d0, off));
                d1 = add2(d1, shfl_xor64(d1, off));
            }
            d0 = add2(d0, bo);
            d1 = add2(d1, bo);
            if (l == 0) {
                float a, b;
                unpack2(d0, a, b);
                outp[(size_t)(baseRow + 0) * Tn] = a;
                outp[(size_t)(baseRow + 1) * Tn] = b;
                unpack2(d1, a, b);
                outp[(size_t)(baseRow + 2) * Tn] = a;
                outp[(size_t)(baseRow + 3) * Tn] = b;
            }
            if (l < 2) {  // u(1) into buffer 0
                int ra = baseRow + 2 * l;
                sZ[0][l][40] = pack2(inputs[(size_t)ra * Tn + 1],
                                     inputs[(size_t)(ra + 1) * Tn + 1]);
            }
        }
    }
    __syncthreads();

    // ---- main loop t = 1 .. 1023 (one __syncthreads per step) ----
    int cur = 0;
    for (int t = 1; t < Tn; t++) {
        // next-input LDG at the top (warp1 lanes 0,1), hidden under the GEMV
        u64 uN = 0ull;
        if (wid == 1 && l < 2 && t + 1 < Tn) {
            int ra = baseRow + 2 * l;
            uN = pack2(inputs[(size_t)ra * Tn + t + 1],
                       inputs[(size_t)(ra + 1) * Tn + t + 1]);
        }

        // ---- GEMV quarter: 5 neurons x 10 k x 2 pairs, weights in regs ----
        u64 acc[5][2];
#pragma unroll
        for (int i = 0; i < 5; i++) { acc[i][0] = bAz[i]; acc[i][1] = bAz[i]; }

#pragma unroll
        for (int p = 0; p < 2; p++) {
            const u64* zb = &sZ[cur][p][k0];
            ulonglong2 z0 = *(const ulonglong2*)(zb + 0);
            ulonglong2 z1 = *(const ulonglong2*)(zb + 2);
            ulonglong2 z2 = *(const ulonglong2*)(zb + 4);
            ulonglong2 z3 = *(const ulonglong2*)(zb + 6);
            ulonglong2 z4 = *(const ulonglong2*)(zb + 8);
#pragma unroll
            for (int i = 0; i < 5; i++) {
                u64 a = acc[i][p];
                a = fma2(z0.x, dupf(wr[i][0]), a);
                a = fma2(z0.y, dupf(wr[i][1]), a);
                a = fma2(z1.x, dupf(wr[i][2]), a);
                a = fma2(z1.y, dupf(wr[i][3]), a);
                a = fma2(z2.x, dupf(wr[i][4]), a);
                a = fma2(z2.y, dupf(wr[i][5]), a);
                a = fma2(z3.x, dupf(wr[i][6]), a);
                a = fma2(z3.y, dupf(wr[i][7]), a);
                a = fma2(z4.x, dupf(wr[i][8]), a);
                a = fma2(z4.y, dupf(wr[i][9]), a);
                acc[i][p] = a;
            }
        }
        {   // u-term (wUz is zero except on kq==3 lanes -> warp-uniform)
            u64 ua = sZ[cur][0][40];
            u64 ub = sZ[cur][1][40];
#pragma unroll
            for (int i = 0; i < 5; i++) {
                acc[i][0] = fma2(ua, wUz[i], acc[i][0]);
                acc[i][1] = fma2(ub, wUz[i], acc[i][1]);
            }
        }

        // ---- combine k-quarters: butterfly over kq bits (xor 1, 2) ----
#pragma unroll
        for (int i = 0; i < 5; i++) {
            acc[i][0] = add2(acc[i][0], shfl_xor64(acc[i][0], 1));
            acc[i][1] = add2(acc[i][1], shfl_xor64(acc[i][1], 1));
            acc[i][0] = add2(acc[i][0], shfl_xor64(acc[i][0], 2));
            acc[i][1] = add2(acc[i][1], shfl_xor64(acc[i][1], 2));
        }

        const int nxt = cur ^ 1;
        if (wid == 0) {
            // a(t) -> next buffer; lane kq stores neuron j0+kq (kq0 also j0+4)
#pragma unroll
            for (int i = 0; i < 5; i++) {
                u64 v0 = lrelu2(acc[i][0], c001);
                u64 v1 = lrelu2(acc[i][1], c001);
                if (i == kq || (kq == 0 && i == 4)) {
                    sZ[nxt][0][j0 + i] = v0;
                    sZ[nxt][1][j0 + i] = v1;
                }
            }
        } else {
            // out(t) inline: lrelu, dot with ow2, reduce over jg, store
            u64 d0 = 0ull, d1 = 0ull;
#pragma unroll
            for (int i = 0; i < 5; i++) {
                d0 = fma2(lrelu2(acc[i][0], c001), rW[i], d0);
                d1 = fma2(lrelu2(acc[i][1], c001), rW[i], d1);
            }
#pragma unroll
            for (int off = 4; off < 32; off <<= 1) {
                d0 = add2(d0, shfl_xor64(d0, off));
                d1 = add2(d1, shfl_xor64(d1, off));
            }
            d0 = add2(d0, bo);
            d1 = add2(d1, bo);
            if (l == 0) {
                float a, b;
                unpack2(d0, a, b);
                outp[(size_t)(baseRow + 0) * Tn + t] = a;
                outp[(size_t)(baseRow + 1) * Tn + t] = b;
                unpack2(d1, a, b);
                outp[(size_t)(baseRow + 2) * Tn + t] = a;
                outp[(size_t)(baseRow + 3) * Tn + t] = b;
            }
            if (l < 2) sZ[nxt][l][40] = uN;   // u(t+1)
        }
        __syncthreads();
        cur = nxt;
    }
}

extern "C" void kernel_launch(void* const* d_in, const int* in_sizes, int n_in,
                              void* d_out, int out_size) {
    const float* inputs = (const float*)d_in[0];
    const float* w1  = (const float*)d_in[1];
    const float* b1  = (const float*)d_in[2];
    const float* w2  = (const float*)d_in[3];
    const float* b2  = (const float*)d_in[4];
    const float* ow1 = (const float*)d_in[5];
    const float* ob1 = (const float*)d_in[6];
    const float* ow2 = (const float*)d_in[7];
    const float* ob2 = (const float*)d_in[8];
    float* out = (float*)d_out;

    rnn_kernel<<<NBLK, NTHR>>>(inputs, w1, b1, w2, b2,
                               ow1, ob1, ow2, ob2, out);
}

// round 14
// speedup vs baseline: 1.2420x; 1.2420x over previous
#include <cuda_runtime.h>

// RNN_64501818851829 — GB300 sm_103a. Round 14.
// Fused recurrence (R9): a(t)=lrelu(W1u·u+M·a(t-1)+c), o(t)=lrelu(OW1u·u+N·a+d),
// out=ow2·o+ob2, M=W1h·W2, N=OW1h·W2 (prologue-computed).
// R13 topology, re-parameterized to avoid register spills:
//   512 blocks x 64 threads (2 warps), 8 rows = 4 f32x2 pairs per block.
//   -> 3.4 blocks/SM needed, 4 fit at <=255 regs (launch_bounds(64,4)).
//   warp0 = h2h neurons 0..39 -> a(t); warp1 = h2o -> out(t) inline.
//   Lane (jg=l>>2: 5 neurons, kq=l&3: 10-k quarter); 50 fused weights
//   pre-dup'd as u64 REGISTERS. k-quarters combined with xor-1/2 butterflies;
//   epilogue warp-uniform: lane kq handles pair kq. Weight LDS in loop: ZERO.
//   One __syncthreads per step.

typedef unsigned long long u64;

static constexpr int Tn = 1024;
static constexpr int NTHR = 64;
static constexpr int NBLK = 512;           // 8 rows per block

__device__ __forceinline__ u64 fma2(u64 a, u64 b, u64 c) {
    u64 d; asm("fma.rn.f32x2 %0, %1, %2, %3;" : "=l"(d) : "l"(a), "l"(b), "l"(c));
    return d;
}
__device__ __forceinline__ u64 add2(u64 a, u64 b) {
    u64 d; asm("add.rn.f32x2 %0, %1, %2;" : "=l"(d) : "l"(a), "l"(b));
    return d;
}
__device__ __forceinline__ u64 mul2(u64 a, u64 b) {
    u64 d; asm("mul.rn.f32x2 %0, %1, %2;" : "=l"(d) : "l"(a), "l"(b));
    return d;
}
__device__ __forceinline__ u64 pack2(float lo, float hi) {
    u64 d; asm("mov.b64 %0, {%1, %2};" : "=l"(d) : "f"(lo), "f"(hi));
    return d;
}
__device__ __forceinline__ void unpack2(u64 v, float& lo, float& hi) {
    asm("mov.b64 {%0, %1}, %2;" : "=f"(lo), "=f"(hi) : "l"(v));
}
__device__ __forceinline__ u64 dupf(float x) {
    u64 d; asm("mov.b64 %0, {%1, %1};" : "=l"(d) : "f"(x));
    return d;
}
// exact leaky-relu(0.01): max(x, 0.01*x)
__device__ __forceinline__ u64 lrelu2(u64 x, u64 c001) {
    u64 m = mul2(x, c001);
    float2 xf = *(float2*)&x, mf = *(float2*)&m, r;
    r.x = fmaxf(xf.x, mf.x);
    r.y = fmaxf(xf.y, mf.y);
    return *(u64*)&r;
}
__device__ __forceinline__ u64 shfl_xor64(u64 v, int m) {
    return __shfl_xor_sync(0xffffffffu, v, m);
}

__global__ void __launch_bounds__(NTHR, 4) rnn_kernel(
    const float* __restrict__ inputs,
    const float* __restrict__ w1,  const float* __restrict__ b1,
    const float* __restrict__ w2,  const float* __restrict__ b2,
    const float* __restrict__ ow1, const float* __restrict__ ob1,
    const float* __restrict__ ow2, const float* __restrict__ ob2,
    float* __restrict__ outp)
{
    __shared__ float sW2f[40 * 40];                 // prologue only
    __shared__ __align__(16) u64 sZ[2][4][42];      // [buf][pair][0..39 z, 40=u]

    const int tid = threadIdx.x;
    const int wid = tid >> 5;      // 0 = h2h (produces a), 1 = h2o (produces out)
    const int l   = tid & 31;
    const int jg  = l >> 2;        // 0..7 -> 5 neurons
    const int kq  = l & 3;         // k-quarter -> 10 k's; also "my pair"
    const int j0  = 5 * jg;
    const int k0  = 10 * kq;
    const int baseRow = blockIdx.x * 8;
    const u64 c001 = dupf(0.01f);

    // ---- stage w2 ----
    for (int i = tid; i < 1600; i += NTHR) sW2f[i] = w2[i];
    __syncthreads();

    // this thread's 5 L1 rows (hidden part, cols 1..40) of its half
    const float* wrow = (wid == 0) ? (w1 + j0 * 41 + 1)
                                   : (ow1 + j0 * 41 + 1);

    // ---- prologue: fused weight slice (W1h @ W2)[j0..j0+4][k0..k0+9] ----
    float wrf[5][10];
    float cd[5];
#pragma unroll
    for (int i = 0; i < 5; i++) {
        cd[i] = 0.0f;
#pragma unroll
        for (int q = 0; q < 10; q++) wrf[i][q] = 0.0f;
    }
    for (int m = 0; m < 40; m++) {
        float av[5];
#pragma unroll
        for (int i = 0; i < 5; i++) av[i] = wrow[i * 41 + m];
        float bm = b2[m];
        float wv[10];
#pragma unroll
        for (int q = 0; q < 10; q++) wv[q] = sW2f[m * 40 + k0 + q];
#pragma unroll
        for (int i = 0; i < 5; i++) {
            cd[i] += av[i] * bm;
#pragma unroll
            for (int q = 0; q < 10; q++) wrf[i][q] += av[i] * wv[q];
        }
    }
    // pre-duplicate fused weights into u64 registers (no per-step MOVs)
    u64 wrd[5][10];
#pragma unroll
    for (int i = 0; i < 5; i++)
#pragma unroll
        for (int q = 0; q < 10; q++) wrd[i][q] = dupf(wrf[i][q]);

    // zero-padded per-lane constants (keep the GEMV warp-uniform)
    u64 bAz[5], wUz[5], rW[5];
#pragma unroll
    for (int i = 0; i < 5; i++) {
        float pb = (wid == 0) ? b1[j0 + i] : ob1[j0 + i];
        bAz[i] = (kq == 0) ? dupf(cd[i] + pb) : 0ull;
        float uw = (wid == 0) ? w1[(j0 + i) * 41] : ow1[(j0 + i) * 41];
        wUz[i] = (kq == 3) ? dupf(uw) : 0ull;
        rW[i]  = (wid == 1) ? dupf(ow2[j0 + i]) : 0ull;
    }
    const u64 bo = dupf(ob2[0]);

    // ---- step t = 0 (h = 0: plain biases, u-column only). Lane's pair = kq.
    {
        int ra = baseRow + 2 * kq;
        u64 u0 = pack2(inputs[(size_t)ra * Tn], inputs[(size_t)(ra + 1) * Tn]);
        if (wid == 0) {
#pragma unroll
            for (int i = 0; i < 5; i++) {
                int n = j0 + i;
                sZ[0][kq][n] =
                    lrelu2(fma2(u0, dupf(w1[n * 41]), dupf(b1[n])), c001);
            }
        } else {
            u64 d = 0ull;
#pragma unroll
            for (int i = 0; i < 5; i++) {
                int n = j0 + i;
                u64 z = lrelu2(fma2(u0, dupf(ow1[n * 41]), dupf(ob1[n])), c001);
                d = fma2(z, rW[i], d);
            }
            d = add2(d, shfl_xor64(d, 4));
            d = add2(d, shfl_xor64(d, 8));
            d = add2(d, shfl_xor64(d, 16));
            d = add2(d, bo);
            if (l < 4) {
                float a, b; unpack2(d, a, b);
                int rr = baseRow + 2 * l;
                outp[(size_t)rr * Tn] = a;
                outp[(size_t)(rr + 1) * Tn] = b;
                sZ[0][l][40] = pack2(inputs[(size_t)rr * Tn + 1],
                                     inputs[(size_t)(rr + 1) * Tn + 1]);
            }
        }
    }
    __syncthreads();

    // ---- main loop t = 1 .. 1023 (one __syncthreads per step) ----
    int cur = 0;
    for (int t = 1; t < Tn; t++) {
        // u(t+1) LDG at the top (warp1 lanes 0-3), hidden under the GEMV
        u64 uN = 0ull;
        if (wid == 1 && l < 4 && t + 1 < Tn) {
            int rr = baseRow + 2 * l;
            uN = pack2(inputs[(size_t)rr * Tn + t + 1],
                       inputs[(size_t)(rr + 1) * Tn + t + 1]);
        }

        // ---- GEMV quarter: 5 neurons x 10 k x 4 pairs, weights in regs ----
        u64 acc[5][4];
#pragma unroll
        for (int i = 0; i < 5; i++)
#pragma unroll
            for (int p = 0; p < 4; p++) acc[i][p] = bAz[i];

#pragma unroll
        for (int p = 0; p < 4; p++) {
            const u64* zb = &sZ[cur][p][k0];
            ulonglong2 z0 = *(const ulonglong2*)(zb + 0);
            ulonglong2 z1 = *(const ulonglong2*)(zb + 2);
            ulonglong2 z2 = *(const ulonglong2*)(zb + 4);
            ulonglong2 z3 = *(const ulonglong2*)(zb + 6);
            ulonglong2 z4 = *(const ulonglong2*)(zb + 8);
#pragma unroll
            for (int i = 0; i < 5; i++) {
                u64 a = acc[i][p];
                a = fma2(z0.x, wrd[i][0], a);
                a = fma2(z0.y, wrd[i][1], a);
                a = fma2(z1.x, wrd[i][2], a);
                a = fma2(z1.y, wrd[i][3], a);
                a = fma2(z2.x, wrd[i][4], a);
                a = fma2(z2.y, wrd[i][5], a);
                a = fma2(z3.x, wrd[i][6], a);
                a = fma2(z3.y, wrd[i][7], a);
                a = fma2(z4.x, wrd[i][8], a);
                a = fma2(z4.y, wrd[i][9], a);
                acc[i][p] = a;
            }
        }
        {   // u-term (wUz zero except kq==3 lanes -> warp-uniform)
            u64 ua0 = sZ[cur][0][40], ua1 = sZ[cur][1][40];
            u64 ua2 = sZ[cur][2][40], ua3 = sZ[cur][3][40];
#pragma unroll
            for (int i = 0; i < 5; i++) {
                acc[i][0] = fma2(ua0, wUz[i], acc[i][0]);
                acc[i][1] = fma2(ua1, wUz[i], acc[i][1]);
                acc[i][2] = fma2(ua2, wUz[i], acc[i][2]);
                acc[i][3] = fma2(ua3, wUz[i], acc[i][3]);
            }
        }

        // ---- combine k-quarters: butterfly xor 1, then xor 2 ----
#pragma unroll
        for (int i = 0; i < 5; i++)
#pragma unroll
            for (int p = 0; p < 4; p++)
                acc[i][p] = add2(acc[i][p], shfl_xor64(acc[i][p], 1));
#pragma unroll
        for (int i = 0; i < 5; i++)
#pragma unroll
            for (int p = 0; p < 4; p++)
                acc[i][p] = add2(acc[i][p], shfl_xor64(acc[i][p], 2));

        const int nxt = cur ^ 1;
        if (wid == 0) {
            // lane kq stores pair kq's 5 neurons (warp-uniform epilogue)
#pragma unroll
            for (int i = 0; i < 5; i++)
                sZ[nxt][kq][j0 + i] = lrelu2(acc[i][kq], c001);
        } else {
            // out(t) inline for pair kq: lrelu, dot ow2, reduce over jg
            u64 d = 0ull;
#pragma unroll
            for (int i = 0; i < 5; i++)
                d = fma2(lrelu2(acc[i][kq], c001), rW[i], d);
            d = add2(d, shfl_xor64(d, 4));
            d = add2(d, shfl_xor64(d, 8));
            d = add2(d, shfl_xor64(d, 16));
            d = add2(d, bo);
            if (l < 4) {
                float a, b; unpack2(d, a, b);
                int rr = baseRow + 2 * l;
                outp[(size_t)rr * Tn + t] = a;
                outp[(size_t)(rr + 1) * Tn + t] = b;
                sZ[nxt][l][40] = uN;   // u(t+1)
            }
        }
        __syncthreads();
        cur = nxt;
    }
}

extern "C" void kernel_launch(void* const* d_in, const int* in_sizes, int n_in,
                              void* d_out, int out_size) {
    const float* inputs = (const float*)d_in[0];
    const float* w1  = (const float*)d_in[1];
    const float* b1  = (const float*)d_in[2];
    const float* w2  = (const float*)d_in[3];
    const float* b2  = (const float*)d_in[4];
    const float* ow1 = (const float*)d_in[5];
    const float* ob1 = (const float*)d_in[6];
    const float* ow2 = (const float*)d_in[7];
    const float* ob2 = (const float*)d_in[8];
    float* out = (float*)d_out;

    rnn_kernel<<<NBLK, NTHR>>>(inputs, w1, b1, w2, b2,
                               ow1, ob1, ow2, ob2, out);
}

// round 15
// speedup vs baseline: 3.0933x; 2.4906x over previous
#include <cuda_runtime.h>

// RNN_64501818851829 — GB300 sm_103a. Round 15.
// = Round 10 (best, 806us: 1024 warp-blocks x 32 thr, 4 rows, fused one-GEMV
//   recurrence, weights in shared, pipelined) + bounded hybrid:
//   * k=0..11 fused weights (60 floats, static-indexed) in REGISTERS
//   * u-column weights (5 u64) in registers
//   -> weight LDS 50->35/thread, u LDS 3->0. L1tex is instruction-count
//   bound (validated: L1 cyc = LDS instr x 2 x warps/SM), so this cuts the
//   dominant resource ~20% with no topology change.

typedef unsigned long long u64;

static constexpr int Tn = 1024;
static constexpr int NTHR = 32;
static constexpr int NBLK = 1024;          // 4 rows per block

__device__ __forceinline__ u64 fma2(u64 a, u64 b, u64 c) {
    u64 d; asm("fma.rn.f32x2 %0, %1, %2, %3;" : "=l"(d) : "l"(a), "l"(b), "l"(c));
    return d;
}
__device__ __forceinline__ u64 add2(u64 a, u64 b) {
    u64 d; asm("add.rn.f32x2 %0, %1, %2;" : "=l"(d) : "l"(a), "l"(b));
    return d;
}
__device__ __forceinline__ u64 mul2(u64 a, u64 b) {
    u64 d; asm("mul.rn.f32x2 %0, %1, %2;" : "=l"(d) : "l"(a), "l"(b));
    return d;
}
__device__ __forceinline__ u64 pack2(float lo, float hi) {
    u64 d; asm("mov.b64 %0, {%1, %2};" : "=l"(d) : "f"(lo), "f"(hi));
    return d;
}
__device__ __forceinline__ void unpack2(u64 v, float& lo, float& hi) {
    asm("mov.b64 {%0, %1}, %2;" : "=f"(lo), "=f"(hi) : "l"(v));
}
__device__ __forceinline__ u64 dupf(float x) {
    u64 d; asm("mov.b64 %0, {%1, %1};" : "=l"(d) : "f"(x));
    return d;
}
// exact leaky-relu(0.01): max(x, 0.01*x)
__device__ __forceinline__ u64 lrelu2(u64 x, u64 c001) {
    u64 m = mul2(x, c001);
    float2 xf = *(float2*)&x, mf = *(float2*)&m, r;
    r.x = fmaxf(xf.x, mf.x);
    r.y = fmaxf(xf.y, mf.y);
    return *(u64*)&r;
}

__global__ void __launch_bounds__(NTHR, 1) rnn_kernel(
    const float* __restrict__ inputs,
    const float* __restrict__ w1,  const float* __restrict__ b1,
    const float* __restrict__ w2,  const float* __restrict__ b2,
    const float* __restrict__ ow1, const float* __restrict__ ob1,
    const float* __restrict__ ow2, const float* __restrict__ ob2,
    float* __restrict__ outp)
{
    // fused weights [M; N] (80 j x 40 k) non-dup: [kq][j] float4 (4 k's)
    __shared__ __align__(16) float fWA[10 * 80 * 4];   // 12800 B
    __shared__ __align__(16) float sW2f[40 * 40];      //  6400 B (prologue)
    __shared__ __align__(16) u64 sZ[2 * 2 * 42];       // [buf][pair][42]; [40]=u
    __shared__ __align__(16) u64 sOutP[2 * 2 * 8];     // [buf][pair][8]

    const int tid = threadIdx.x;
    const int baseRow = blockIdx.x * 4;
    const int s1 = tid & 1, jg1 = tid >> 1;    // pair, neuron-group (5 neurons)
    const bool isH2H = (jg1 < 8);
    const int j0 = 5 * jg1;                    // global neuron base (0..75)
    const u64 c001 = dupf(0.01f);

    // ---- stage w2 ----
    for (int idx = tid; idx < 1600; idx += NTHR) sW2f[idx] = w2[idx];
    __syncwarp();

    // global pointer to this thread's 5 rows of the L1 hidden block (stride 41)
    const float* wrow = isH2H ? (w1 + j0 * 41 + 1)
                              : (ow1 + (j0 - 40) * 41 + 1);

    // ---- prologue: fused M/N = W1h @ W2 -> fWA (s1==0 twin computes) ----
    if (s1 == 0) {
        for (int pass = 0; pass < 4; pass++) {
            const int k0 = 10 * pass;
            u64 acc2[5][5];
#pragma unroll
            for (int i = 0; i < 5; i++)
#pragma unroll
                for (int q = 0; q < 5; q++) acc2[i][q] = 0ull;
            for (int m = 0; m < 40; m++) {
                u64 a[5];
#pragma unroll
                for (int i = 0; i < 5; i++) a[i] = dupf(wrow[i * 41 + m]);
                const u64* wv2 = (const u64*)(sW2f + m * 40 + k0);
#pragma unroll
                for (int q = 0; q < 5; q++) {
                    u64 wv = wv2[q];
#pragma unroll
                    for (int i = 0; i < 5; i++)
                        acc2[i][q] = fma2(a[i], wv, acc2[i][q]);
                }
            }
#pragma unroll
            for (int i = 0; i < 5; i++)
#pragma unroll
                for (int q = 0; q < 5; q++) {
                    float lo, hi; unpack2(acc2[i][q], lo, hi);
                    int k = k0 + 2 * q;
                    fWA[((k >> 2) * 80 + (j0 + i)) * 4 + (k & 3)] = lo;
                    k++;
                    fWA[((k >> 2) * 80 + (j0 + i)) * 4 + (k & 3)] = hi;
                }
        }
    }

    // ---- fused biases c/d, u-weights (registers), out-dot weights ----
    u64 bA[5], rW[5], wu[5];
    {
        float cd[5] = {0, 0, 0, 0, 0};
        for (int m = 0; m < 40; m++) {
            float bv = b2[m];
#pragma unroll
            for (int i = 0; i < 5; i++) cd[i] += wrow[i * 41 + m] * bv;
        }
#pragma unroll
        for (int i = 0; i < 5; i++) {
            float base = isH2H ? b1[j0 + i] : ob1[j0 - 40 + i];
            bA[i] = dupf(cd[i] + base);
            rW[i] = isH2H ? 0ull : dupf(ow2[j0 - 40 + i]);
            wu[i] = dupf(isH2H ? w1[(j0 + i) * 41] : ow1[(j0 - 40 + i) * 41]);
        }
    }
    const u64 bo = dupf(ob2[0]);
    __syncwarp();   // fWA visible to all lanes

    // ---- register slice of fused weights: k = 0..11 (60 floats) ----
    float wreg[5][12];
#pragma unroll
    for (int i = 0; i < 5; i++)
#pragma unroll
        for (int q = 0; q < 12; q++)
            wreg[i][q] = fWA[((q >> 2) * 80 + (j0 + i)) * 4 + (q & 3)];

    // ---- special step t = 0 (h = 0: plain biases, u-column only) ----
    {
        const int pr0 = baseRow + 2 * s1, pr1 = pr0 + 1;
        u64 u0 = pack2(inputs[(size_t)pr0 * Tn], inputs[(size_t)pr1 * Tn]);
        u64 z[5];
#pragma unroll
        for (int i = 0; i < 5; i++) {
            float pbv = isH2H ? b1[j0 + i] : ob1[j0 - 40 + i];
            z[i] = lrelu2(fma2(u0, wu[i], dupf(pbv)), c001);
        }
        if (isH2H) {
            u64* d = sZ + s1 * 42 + j0;
#pragma unroll
            for (int i = 0; i < 5; i++) d[i] = z[i];
        } else {
            u64 p = mul2(z[0], rW[0]);
            p = fma2(z[1], rW[1], p); p = fma2(z[2], rW[2], p);
            p = fma2(z[3], rW[3], p); p = fma2(z[4], rW[4], p);
            sOutP[s1 * 8 + (jg1 - 8)] = p;
        }
        if (tid < 2)   // u(1) into buffer 0
            sZ[tid * 42 + 40] = pack2(inputs[(size_t)(baseRow + 2 * tid) * Tn + 1],
                                      inputs[(size_t)(baseRow + 2 * tid + 1) * Tn + 1]);
    }
    __syncwarp();

    // ---- main loop t = 1 .. 1023 ----
    const float4* wA4 = (const float4*)fWA + jg1 * 5;
    const int r0 = baseRow + 2 * tid;          // rows for tid<2 duties
    const int r1v = r0 + 1;
    int cur = 0;
    for (int t = 1; t < Tn; t++) {
        // issue next-input LDG at the very top (hidden under the GEMV)
        u64 uN = 0ull;
        if (tid < 2 && t + 1 < Tn)
            uN = pack2(inputs[(size_t)r0 * Tn + t + 1],
                       inputs[(size_t)r1v * Tn + t + 1]);

        // reduce out(t-1) from previous step's partials
        if (tid < 2) {
            const ulonglong2* pp = (const ulonglong2*)(sOutP + cur * 16 + tid * 8);
            ulonglong2 p0 = pp[0], p1 = pp[1], p2 = pp[2], p3 = pp[3];
            u64 s = add2(add2(add2(p0.x, p0.y), add2(p1.x, p1.y)),
                         add2(add2(p2.x, p2.y), add2(p3.x, p3.y)));
            s = add2(s, bo);
            float lo, hi; unpack2(s, lo, hi);
            outp[(size_t)r0 * Tn + (t - 1)] = lo;
            outp[(size_t)r1v * Tn + (t - 1)] = hi;
        }

        const u64* zb = sZ + cur * 84 + s1 * 42;
        u64 a0 = bA[0], a1 = bA[1], a2 = bA[2], a3 = bA[3], a4 = bA[4];

        // ---- part 1: k = 0..11 from register weights ----
        ulonglong2 y0 = *(const ulonglong2*)(zb + 0);
        ulonglong2 y1 = *(const ulonglong2*)(zb + 2);
        ulonglong2 y2 = *(const ulonglong2*)(zb + 4);
        ulonglong2 y3 = *(const ulonglong2*)(zb + 6);
        ulonglong2 y4 = *(const ulonglong2*)(zb + 8);
        ulonglong2 y5 = *(const ulonglong2*)(zb + 10);
        // preload for shared part (kq = 3)
        ulonglong2 z01 = *(const ulonglong2*)(zb + 12);
        ulonglong2 z23 = *(const ulonglong2*)(zb + 14);
        float4 v0 = wA4[3 * 80 + 0], v1 = wA4[3 * 80 + 1], v2 = wA4[3 * 80 + 2],
               v3 = wA4[3 * 80 + 3], v4 = wA4[3 * 80 + 4];

#pragma unroll
        for (int i = 0; i < 5; i++) {
            u64 a = (i == 0) ? a0 : (i == 1) ? a1 : (i == 2) ? a2
                                  : (i == 3) ? a3 : a4;
            a = fma2(y0.x, dupf(wreg[i][0]),  a);
            a = fma2(y0.y, dupf(wreg[i][1]),  a);
            a = fma2(y1.x, dupf(wreg[i][2]),  a);
            a = fma2(y1.y, dupf(wreg[i][3]),  a);
            a = fma2(y2.x, dupf(wreg[i][4]),  a);
            a = fma2(y2.y, dupf(wreg[i][5]),  a);
            a = fma2(y3.x, dupf(wreg[i][6]),  a);
            a = fma2(y3.y, dupf(wreg[i][7]),  a);
            a = fma2(y4.x, dupf(wreg[i][8]),  a);
            a = fma2(y4.y, dupf(wreg[i][9]),  a);
            a = fma2(y5.x, dupf(wreg[i][10]), a);
            a = fma2(y5.y, dupf(wreg[i][11]), a);
            if (i == 0) a0 = a; else if (i == 1) a1 = a; else if (i == 2) a2 = a;
            else if (i == 3) a3 = a; else a4 = a;
        }

        // ---- part 2: kq = 3..9 from shared, software-pipelined ----
#pragma unroll
        for (int kq = 3; kq < 10; kq++) {
            ulonglong2 nz01, nz23;
            float4 n0, n1, n2, n3, n4;
            if (kq < 9) {
                nz01 = *(const ulonglong2*)(zb + 4 * (kq + 1));
                nz23 = *(const ulonglong2*)(zb + 4 * (kq + 1) + 2);
                n0 = wA4[(kq + 1) * 80 + 0];
                n1 = wA4[(kq + 1) * 80 + 1];
                n2 = wA4[(kq + 1) * 80 + 2];
                n3 = wA4[(kq + 1) * 80 + 3];
                n4 = wA4[(kq + 1) * 80 + 4];
            }
            u64 dx;
            dx = dupf(v0.x); a0 = fma2(z01.x, dx, a0);
            dx = dupf(v0.y); a0 = fma2(z01.y, dx, a0);
            dx = dupf(v0.z); a0 = fma2(z23.x, dx, a0);
            dx = dupf(v0.w); a0 = fma2(z23.y, dx, a0);
            dx = dupf(v1.x); a1 = fma2(z01.x, dx, a1);
            dx = dupf(v1.y); a1 = fma2(z01.y, dx, a1);
            dx = dupf(v1.z); a1 = fma2(z23.x, dx, a1);
            dx = dupf(v1.w); a1 = fma2(z23.y, dx, a1);
            dx = dupf(v2.x); a2 = fma2(z01.x, dx, a2);
            dx = dupf(v2.y); a2 = fma2(z01.y, dx, a2);
            dx = dupf(v2.z); a2 = fma2(z23.x, dx, a2);
            dx = dupf(v2.w); a2 = fma2(z23.y, dx, a2);
            dx = dupf(v3.x); a3 = fma2(z01.x, dx, a3);
            dx = dupf(v3.y); a3 = fma2(z01.y, dx, a3);
            dx = dupf(v3.z); a3 = fma2(z23.x, dx, a3);
            dx = dupf(v3.w); a3 = fma2(z23.y, dx, a3);
            dx = dupf(v4.x); a4 = fma2(z01.x, dx, a4);
            dx = dupf(v4.y); a4 = fma2(z01.y, dx, a4);
            dx = dupf(v4.z); a4 = fma2(z23.x, dx, a4);
            dx = dupf(v4.w); a4 = fma2(z23.y, dx, a4);
            if (kq < 9) {
                z01 = nz01; z23 = nz23;
                v0 = n0; v1 = n1; v2 = n2; v3 = n3; v4 = n4;
            }
        }
        {   // u-term (weights in registers)
            u64 ua = zb[40];
            a0 = fma2(ua, wu[0], a0);
            a1 = fma2(ua, wu[1], a1);
            a2 = fma2(ua, wu[2], a2);
            a3 = fma2(ua, wu[3], a3);
            a4 = fma2(ua, wu[4], a4);
        }
        a0 = lrelu2(a0, c001);
        a1 = lrelu2(a1, c001);
        a2 = lrelu2(a2, c001);
        a3 = lrelu2(a3, c001);
        a4 = lrelu2(a4, c001);

        const int nxt = cur ^ 1;
        if (isH2H) {  // a(t) -> next buffer
            u64* d = sZ + nxt * 84 + s1 * 42 + j0;
            d[0] = a0; d[1] = a1; d[2] = a2; d[3] = a3; d[4] = a4;
        } else {      // o(t) -> out-dot partials (reduced next step)
            u64 p = mul2(a0, rW[0]);
            p = fma2(a1, rW[1], p); p = fma2(a2, rW[2], p);
            p = fma2(a3, rW[3], p); p = fma2(a4, rW[4], p);
            sOutP[nxt * 16 + s1 * 8 + (jg1 - 8)] = p;
        }
        if (tid < 2)   // u(t+1) into next buffer
            sZ[nxt * 84 + tid * 42 + 40] = uN;
        __syncwarp();
        cur = nxt;
    }

    // final out(1023)
    if (tid < 2) {
        const ulonglong2* pp = (const ulonglong2*)(sOutP + cur * 16 + tid * 8);
        ulonglong2 p0 = pp[0], p1 = pp[1], p2 = pp[2], p3 = pp[3];
        u64 s = add2(add2(add2(p0.x, p0.y), add2(p1.x, p1.y)),
                     add2(add2(p2.x, p2.y), add2(p3.x, p3.y)));
        s = add2(s, bo);
        float lo, hi; unpack2(s, lo, hi);
        outp[(size_t)r0 * Tn + (Tn - 1)] = lo;
        outp[(size_t)r1v * Tn + (Tn - 1)] = hi;
    }
}

extern "C" void kernel_launch(void* const* d_in, const int* in_sizes, int n_in,
                              void* d_out, int out_size) {
    const float* inputs = (const float*)d_in[0];
    const float* w1  = (const float*)d_in[1];
    const float* b1  = (const float*)d_in[2];
    const float* w2  = (const float*)d_in[3];
    const float* b2  = (const float*)d_in[4];
    const float* ow1 = (const float*)d_in[5];
    const float* ob1 = (const float*)d_in[6];
    const float* ow2 = (const float*)d_in[7];
    const float* ob2 = (const float*)d_in[8];
    float* out = (float*)d_out;

    rnn_kernel<<<NBLK, NTHR>>>(inputs, w1, b1, w2, b2,
                               ow1, ob1, ow2, ob2, out);
}

// round 16
// speedup vs baseline: 3.2160x; 1.0397x over previous
#include <cuda_runtime.h>

// RNN_64501818851829 — GB300 sm_103a. Round 16.
// = Round 15 (792us) with deeper latency hiding, same topology
//   (1024 warp-blocks x 32 thr, 4 rows, fused one-GEMV recurrence):
//   * register weight slice extended to k=0..15 (80 floats)
//   * ALL shared-part stage preloads + u-load hoisted to step top,
//     hidden under the 80 register-weight FMA2s of part 1
//   * depth-2 software pipeline for the remaining 6 shared kq

typedef unsigned long long u64;

static constexpr int Tn = 1024;
static constexpr int NTHR = 32;
static constexpr int NBLK = 1024;          // 4 rows per block

__device__ __forceinline__ u64 fma2(u64 a, u64 b, u64 c) {
    u64 d; asm("fma.rn.f32x2 %0, %1, %2, %3;" : "=l"(d) : "l"(a), "l"(b), "l"(c));
    return d;
}
__device__ __forceinline__ u64 add2(u64 a, u64 b) {
    u64 d; asm("add.rn.f32x2 %0, %1, %2;" : "=l"(d) : "l"(a), "l"(b));
    return d;
}
__device__ __forceinline__ u64 mul2(u64 a, u64 b) {
    u64 d; asm("mul.rn.f32x2 %0, %1, %2;" : "=l"(d) : "l"(a), "l"(b));
    return d;
}
__device__ __forceinline__ u64 pack2(float lo, float hi) {
    u64 d; asm("mov.b64 %0, {%1, %2};" : "=l"(d) : "f"(lo), "f"(hi));
    return d;
}
__device__ __forceinline__ void unpack2(u64 v, float& lo, float& hi) {
    asm("mov.b64 {%0, %1}, %2;" : "=f"(lo), "=f"(hi) : "l"(v));
}
__device__ __forceinline__ u64 dupf(float x) {
    u64 d; asm("mov.b64 %0, {%1, %1};" : "=l"(d) : "f"(x));
    return d;
}
// exact leaky-relu(0.01): max(x, 0.01*x)
__device__ __forceinline__ u64 lrelu2(u64 x, u64 c001) {
    u64 m = mul2(x, c001);
    float2 xf = *(float2*)&x, mf = *(float2*)&m, r;
    r.x = fmaxf(xf.x, mf.x);
    r.y = fmaxf(xf.y, mf.y);
    return *(u64*)&r;
}

__global__ void __launch_bounds__(NTHR, 1) rnn_kernel(
    const float* __restrict__ inputs,
    const float* __restrict__ w1,  const float* __restrict__ b1,
    const float* __restrict__ w2,  const float* __restrict__ b2,
    const float* __restrict__ ow1, const float* __restrict__ ob1,
    const float* __restrict__ ow2, const float* __restrict__ ob2,
    float* __restrict__ outp)
{
    // fused weights [M; N] (80 j x 40 k) non-dup: [kq][j] float4 (4 k's)
    __shared__ __align__(16) float fWA[10 * 80 * 4];   // 12800 B
    __shared__ __align__(16) float sW2f[40 * 40];      //  6400 B (prologue)
    __shared__ __align__(16) u64 sZ[2 * 2 * 42];       // [buf][pair][42]; [40]=u
    __shared__ __align__(16) u64 sOutP[2 * 2 * 8];     // [buf][pair][8]

    const int tid = threadIdx.x;
    const int baseRow = blockIdx.x * 4;
    const int s1 = tid & 1, jg1 = tid >> 1;    // pair, neuron-group (5 neurons)
    const bool isH2H = (jg1 < 8);
    const int j0 = 5 * jg1;                    // global neuron base (0..75)
    const u64 c001 = dupf(0.01f);

    // ---- stage w2 ----
    for (int idx = tid; idx < 1600; idx += NTHR) sW2f[idx] = w2[idx];
    __syncwarp();

    // global pointer to this thread's 5 rows of the L1 hidden block (stride 41)
    const float* wrow = isH2H ? (w1 + j0 * 41 + 1)
                              : (ow1 + (j0 - 40) * 41 + 1);

    // ---- prologue: fused M/N = W1h @ W2 -> fWA (s1==0 twin computes) ----
    if (s1 == 0) {
        for (int pass = 0; pass < 4; pass++) {
            const int k0 = 10 * pass;
            u64 acc2[5][5];
#pragma unroll
            for (int i = 0; i < 5; i++)
#pragma unroll
                for (int q = 0; q < 5; q++) acc2[i][q] = 0ull;
            for (int m = 0; m < 40; m++) {
                u64 a[5];
#pragma unroll
                for (int i = 0; i < 5; i++) a[i] = dupf(wrow[i * 41 + m]);
                const u64* wv2 = (const u64*)(sW2f + m * 40 + k0);
#pragma unroll
                for (int q = 0; q < 5; q++) {
                    u64 wv = wv2[q];
#pragma unroll
                    for (int i = 0; i < 5; i++)
                        acc2[i][q] = fma2(a[i], wv, acc2[i][q]);
                }
            }
#pragma unroll
            for (int i = 0; i < 5; i++)
#pragma unroll
                for (int q = 0; q < 5; q++) {
                    float lo, hi; unpack2(acc2[i][q], lo, hi);
                    int k = k0 + 2 * q;
                    fWA[((k >> 2) * 80 + (j0 + i)) * 4 + (k & 3)] = lo;
                    k++;
                    fWA[((k >> 2) * 80 + (j0 + i)) * 4 + (k & 3)] = hi;
                }
        }
    }

    // ---- fused biases c/d, u-weights (registers), out-dot weights ----
    u64 bA[5], rW[5], wu[5];
    {
        float cd[5] = {0, 0, 0, 0, 0};
        for (int m = 0; m < 40; m++) {
            float bv = b2[m];
#pragma unroll
            for (int i = 0; i < 5; i++) cd[i] += wrow[i * 41 + m] * bv;
        }
#pragma unroll
        for (int i = 0; i < 5; i++) {
            float base = isH2H ? b1[j0 + i] : ob1[j0 - 40 + i];
            bA[i] = dupf(cd[i] + base);
            rW[i] = isH2H ? 0ull : dupf(ow2[j0 - 40 + i]);
            wu[i] = dupf(isH2H ? w1[(j0 + i) * 41] : ow1[(j0 - 40 + i) * 41]);
        }
    }
    const u64 bo = dupf(ob2[0]);
    __syncwarp();   // fWA visible to all lanes

    // ---- register slice of fused weights: k = 0..15 (80 floats) ----
    float wreg[5][16];
#pragma unroll
    for (int i = 0; i < 5; i++)
#pragma unroll
        for (int q = 0; q < 16; q++)
            wreg[i][q] = fWA[((q >> 2) * 80 + (j0 + i)) * 4 + (q & 3)];

    // ---- special step t = 0 (h = 0: plain biases, u-column only) ----
    {
        const int pr0 = baseRow + 2 * s1, pr1 = pr0 + 1;
        u64 u0 = pack2(inputs[(size_t)pr0 * Tn], inputs[(size_t)pr1 * Tn]);
        u64 z[5];
#pragma unroll
        for (int i = 0; i < 5; i++) {
            float pbv = isH2H ? b1[j0 + i] : ob1[j0 - 40 + i];
            z[i] = lrelu2(fma2(u0, wu[i], dupf(pbv)), c001);
        }
        if (isH2H) {
            u64* d = sZ + s1 * 42 + j0;
#pragma unroll
            for (int i = 0; i < 5; i++) d[i] = z[i];
        } else {
            u64 p = mul2(z[0], rW[0]);
            p = fma2(z[1], rW[1], p); p = fma2(z[2], rW[2], p);
            p = fma2(z[3], rW[3], p); p = fma2(z[4], rW[4], p);
            sOutP[s1 * 8 + (jg1 - 8)] = p;
        }
        if (tid < 2)   // u(1) into buffer 0
            sZ[tid * 42 + 40] = pack2(inputs[(size_t)(baseRow + 2 * tid) * Tn + 1],
                                      inputs[(size_t)(baseRow + 2 * tid + 1) * Tn + 1]);
    }
    __syncwarp();

    // ---- main loop t = 1 .. 1023 ----
    const float4* wA4 = (const float4*)fWA + jg1 * 5;
    const int r0 = baseRow + 2 * tid;          // rows for tid<2 duties
    const int r1v = r0 + 1;
    int cur = 0;
    for (int t = 1; t < Tn; t++) {
        // issue next-input LDG at the very top (hidden under the GEMV)
        u64 uN = 0ull;
        if (tid < 2 && t + 1 < Tn)
            uN = pack2(inputs[(size_t)r0 * Tn + t + 1],
                       inputs[(size_t)r1v * Tn + t + 1]);

        // reduce out(t-1) from previous step's partials
        if (tid < 2) {
            const ulonglong2* pp = (const ulonglong2*)(sOutP + cur * 16 + tid * 8);
            ulonglong2 p0 = pp[0], p1 = pp[1], p2 = pp[2], p3 = pp[3];
            u64 s = add2(add2(add2(p0.x, p0.y), add2(p1.x, p1.y)),
                         add2(add2(p2.x, p2.y), add2(p3.x, p3.y)));
            s = add2(s, bo);
            float lo, hi; unpack2(s, lo, hi);
            outp[(size_t)r0 * Tn + (t - 1)] = lo;
            outp[(size_t)r1v * Tn + (t - 1)] = hi;
        }

        const u64* zb = sZ + cur * 84 + s1 * 42;
        u64 a0 = bA[0], a1 = bA[1], a2 = bA[2], a3 = bA[3], a4 = bA[4];

        // ---- front-loaded LDS: part-1 z (k0..15), u, and 2 pipeline stages ----
        ulonglong2 y0 = *(const ulonglong2*)(zb + 0);
        ulonglong2 y1 = *(const ulonglong2*)(zb + 2);
        ulonglong2 y2 = *(const ulonglong2*)(zb + 4);
        ulonglong2 y3 = *(const ulonglong2*)(zb + 6);
        ulonglong2 y4 = *(const ulonglong2*)(zb + 8);
        ulonglong2 y5 = *(const ulonglong2*)(zb + 10);
        ulonglong2 y6 = *(const ulonglong2*)(zb + 12);
        ulonglong2 y7 = *(const ulonglong2*)(zb + 14);
        u64 ua = zb[40];
        // depth-2 pipeline stages for shared part (kq = 4, 5)
        ulonglong2 qz01[2], qz23[2];
        float4 qv0[2], qv1[2], qv2[2], qv3[2], qv4[2];
#pragma unroll
        for (int s = 0; s < 2; s++) {
            qz01[s] = *(const ulonglong2*)(zb + 4 * (4 + s));
            qz23[s] = *(const ulonglong2*)(zb + 4 * (4 + s) + 2);
            qv0[s] = wA4[(4 + s) * 80 + 0];
            qv1[s] = wA4[(4 + s) * 80 + 1];
            qv2[s] = wA4[(4 + s) * 80 + 2];
            qv3[s] = wA4[(4 + s) * 80 + 3];
            qv4[s] = wA4[(4 + s) * 80 + 4];
        }

        // ---- part 1: k = 0..15 from register weights (no LDS deps) ----
#pragma unroll
        for (int i = 0; i < 5; i++) {
            u64 a = (i == 0) ? a0 : (i == 1) ? a1 : (i == 2) ? a2
                                  : (i == 3) ? a3 : a4;
            a = fma2(y0.x, dupf(wreg[i][0]),  a);
            a = fma2(y0.y, dupf(wreg[i][1]),  a);
            a = fma2(y1.x, dupf(wreg[i][2]),  a);
            a = fma2(y1.y, dupf(wreg[i][3]),  a);
            a = fma2(y2.x, dupf(wreg[i][4]),  a);
            a = fma2(y2.y, dupf(wreg[i][5]),  a);
            a = fma2(y3.x, dupf(wreg[i][6]),  a);
            a = fma2(y3.y, dupf(wreg[i][7]),  a);
            a = fma2(y4.x, dupf(wreg[i][8]),  a);
            a = fma2(y4.y, dupf(wreg[i][9]),  a);
            a = fma2(y5.x, dupf(wreg[i][10]), a);
            a = fma2(y5.y, dupf(wreg[i][11]), a);
            a = fma2(y6.x, dupf(wreg[i][12]), a);
            a = fma2(y6.y, dupf(wreg[i][13]), a);
            a = fma2(y7.x, dupf(wreg[i][14]), a);
            a = fma2(y7.y, dupf(wreg[i][15]), a);
            if (i == 0) a0 = a; else if (i == 1) a1 = a; else if (i == 2) a2 = a;
            else if (i == 3) a3 = a; else a4 = a;
        }

        // ---- part 2: kq = 4..9 from shared, depth-2 pipelined ----
#pragma unroll
        for (int kq = 4; kq < 10; kq++) {
            const int sl = kq & 1;
            ulonglong2 cz01 = qz01[sl], cz23 = qz23[sl];
            float4 c0 = qv0[sl], c1 = qv1[sl], c2 = qv2[sl],
                   c3 = qv3[sl], c4 = qv4[sl];
            if (kq + 2 < 10) {   // refill this slot 2 iterations ahead
                qz01[sl] = *(const ulonglong2*)(zb + 4 * (kq + 2));
                qz23[sl] = *(const ulonglong2*)(zb + 4 * (kq + 2) + 2);
                qv0[sl] = wA4[(kq + 2) * 80 + 0];
                qv1[sl] = wA4[(kq + 2) * 80 + 1];
                qv2[sl] = wA4[(kq + 2) * 80 + 2];
                qv3[sl] = wA4[(kq + 2) * 80 + 3];
                qv4[sl] = wA4[(kq + 2) * 80 + 4];
            }
            u64 dx;
            dx = dupf(c0.x); a0 = fma2(cz01.x, dx, a0);
            dx = dupf(c0.y); a0 = fma2(cz01.y, dx, a0);
            dx = dupf(c0.z); a0 = fma2(cz23.x, dx, a0);
            dx = dupf(c0.w); a0 = fma2(cz23.y, dx, a0);
            dx = dupf(c1.x); a1 = fma2(cz01.x, dx, a1);
            dx = dupf(c1.y); a1 = fma2(cz01.y, dx, a1);
            dx = dupf(c1.z); a1 = fma2(cz23.x, dx, a1);
            dx = dupf(c1.w); a1 = fma2(cz23.y, dx, a1);
            dx = dupf(c2.x); a2 = fma2(cz01.x, dx, a2);
            dx = dupf(c2.y); a2 = fma2(cz01.y, dx, a2);
            dx = dupf(c2.z); a2 = fma2(cz23.x, dx, a2);
            dx = dupf(c2.w); a2 = fma2(cz23.y, dx, a2);
            dx = dupf(c3.x); a3 = fma2(cz01.x, dx, a3);
            dx = dupf(c3.y); a3 = fma2(cz01.y, dx, a3);
            dx = dupf(c3.z); a3 = fma2(cz23.x, dx, a3);
            dx = dupf(c3.w); a3 = fma2(cz23.y, dx, a3);
            dx = dupf(c4.x); a4 = fma2(cz01.x, dx, a4);
            dx = dupf(c4.y); a4 = fma2(cz01.y, dx, a4);
            dx = dupf(c4.z); a4 = fma2(cz23.x, dx, a4);
            dx = dupf(c4.w); a4 = fma2(cz23.y, dx, a4);
        }
        {   // u-term (ua loaded at step top, weights in registers)
            a0 = fma2(ua, wu[0], a0);
            a1 = fma2(ua, wu[1], a1);
            a2 = fma2(ua, wu[2], a2);
            a3 = fma2(ua, wu[3], a3);
            a4 = fma2(ua, wu[4], a4);
        }
        a0 = lrelu2(a0, c001);
        a1 = lrelu2(a1, c001);
        a2 = lrelu2(a2, c001);
        a3 = lrelu2(a3, c001);
        a4 = lrelu2(a4, c001);

        const int nxt = cur ^ 1;
        if (isH2H) {  // a(t) -> next buffer
            u64* d = sZ + nxt * 84 + s1 * 42 + j0;
            d[0] = a0; d[1] = a1; d[2] = a2; d[3] = a3; d[4] = a4;
        } else {      // o(t) -> out-dot partials (reduced next step)
            u64 p = mul2(a0, rW[0]);
            p = fma2(a1, rW[1], p); p = fma2(a2, rW[2], p);
            p = fma2(a3, rW[3], p); p = fma2(a4, rW[4], p);
            sOutP[nxt * 16 + s1 * 8 + (jg1 - 8)] = p;
        }
        if (tid < 2)   // u(t+1) into next buffer
            sZ[nxt * 84 + tid * 42 + 40] = uN;
        __syncwarp();
        cur = nxt;
    }

    // final out(1023)
    if (tid < 2) {
        const ulonglong2* pp = (const ulonglong2*)(sOutP + cur * 16 + tid * 8);
        ulonglong2 p0 = pp[0], p1 = pp[1], p2 = pp[2], p3 = pp[3];
        u64 s = add2(add2(add2(p0.x, p0.y), add2(p1.x, p1.y)),
                     add2(add2(p2.x, p2.y), add2(p3.x, p3.y)));
        s = add2(s, bo);
        float lo, hi; unpack2(s, lo, hi);
        outp[(size_t)r0 * Tn + (Tn - 1)] = lo;
        outp[(size_t)r1v * Tn + (Tn - 1)] = hi;
    }
}

extern "C" void kernel_launch(void* const* d_in, const int* in_sizes, int n_in,
                              void* d_out, int out_size) {
    const float* inputs = (const float*)d_in[0];
    const float* w1  = (const float*)d_in[1];
    const float* b1  = (const float*)d_in[2];
    const float* w2  = (const float*)d_in[3];
    const float* b2  = (const float*)d_in[4];
    const float* ow1 = (const float*)d_in[5];
    const float* ob1 = (const float*)d_in[6];
    const float* ow2 = (const float*)d_in[7];
    const float* ob2 = (const float*)d_in[8];
    float* out = (float*)d_out;

    rnn_kernel<<<NBLK, NTHR>>>(inputs, w1, b1, w2, b2,
                               ow1, ob1, ow2, ob2, out);
}